// round 1
// baseline (speedup 1.0000x reference)
#include <cuda_runtime.h>
#include <cuda_bf16.h>

#define NN 100000
#define EE 1600000
#define FF 64

// Scratch: Tx1 and raw A@Tx1 (Chebyshev recurrence folded into GEMM weights).
__device__ __align__(16) float g_t1[NN * FF];
__device__ __align__(16) float g_t2[NN * FF];
__device__ int g_rowptr[NN + 1];

// ---------------------------------------------------------------------------
// Kernel 1: CSR row pointers via binary search (rows is sorted).
// ---------------------------------------------------------------------------
__global__ void build_rowptr(const int* __restrict__ rows) {
    int i = blockIdx.x * blockDim.x + threadIdx.x;
    if (i > NN) return;
    int lo = 0, hi = EE;
    while (lo < hi) {
        int mid = (lo + hi) >> 1;
        if (rows[mid] < i) lo = mid + 1; else hi = mid;
    }
    g_rowptr[i] = lo;
}

// ---------------------------------------------------------------------------
// Kernel 2/3: SPMM, warp per row, float2 per lane, 4-edge unroll (MLP=4).
// PASS 0: src = x (param), dst = g_t1.  PASS 1: src = g_t1, dst = g_t2.
// ---------------------------------------------------------------------------
template <int PASS>
__global__ void spmm_kernel(const float* __restrict__ x,
                            const int* __restrict__ cols,
                            const float* __restrict__ vals) {
    int row = blockIdx.x * 8 + (threadIdx.x >> 5);
    if (row >= NN) return;
    int lane = threadIdx.x & 31;

    const float2* __restrict__ h2 =
        (PASS == 0) ? (const float2*)x : (const float2*)g_t1;
    float2* __restrict__ dst =
        (PASS == 0) ? (float2*)g_t1 : (float2*)g_t2;

    int s = g_rowptr[row];
    int e = g_rowptr[row + 1];

    float accx = 0.f, accy = 0.f;
    int i = s;
    for (; i + 4 <= e; i += 4) {
        int   c0 = cols[i],  c1 = cols[i + 1], c2 = cols[i + 2], c3 = cols[i + 3];
        float v0 = vals[i],  v1 = vals[i + 1], v2 = vals[i + 2], v3 = vals[i + 3];
        float2 a = h2[c0 * 32 + lane];
        float2 b = h2[c1 * 32 + lane];
        float2 c = h2[c2 * 32 + lane];
        float2 d = h2[c3 * 32 + lane];
        accx += v0 * a.x; accy += v0 * a.y;
        accx += v1 * b.x; accy += v1 * b.y;
        accx += v2 * c.x; accy += v2 * c.y;
        accx += v3 * d.x; accy += v3 * d.y;
    }
    for (; i < e; ++i) {
        int   c = cols[i];
        float v = vals[i];
        float2 a = h2[c * 32 + lane];
        accx += v * a.x; accy += v * a.y;
    }
    dst[row * 32 + lane] = make_float2(accx, accy);
}

// ---------------------------------------------------------------------------
// Kernel 4: out = [x | t1 | t2raw] @ [W0-W2 ; W1 ; 2*W2] + bias
// Tile: 64 nodes x 64 cols per block, 256 threads, 4x4 register tile each.
// ---------------------------------------------------------------------------
#define GEMM_SMEM (192 * 64 * 4 + 64 * 196 * 4)

__global__ void __launch_bounds__(256, 2)
gemm_out_kernel(const float* __restrict__ x,
                const float* __restrict__ weight,
                const float* __restrict__ bias,
                float* __restrict__ out) {
    extern __shared__ float smem[];
    float* sW = smem;            // [192][64]
    float* sA = smem + 192 * 64; // [64][196] padded

    const int tid = threadIdx.x;
    const int node0 = blockIdx.x * 64;

    // Stage folded weights: k<64 -> W0-W2 ; k<128 -> W1 ; else -> 2*W2
    for (int idx = tid; idx < 192 * 64; idx += 256) {
        int k = idx >> 6, j = idx & 63;
        float wv;
        if (k < 64)        wv = weight[k * 64 + j] - weight[2 * 4096 + k * 64 + j];
        else if (k < 128)  wv = weight[4096 + (k - 64) * 64 + j];
        else               wv = 2.0f * weight[8192 + (k - 128) * 64 + j];
        sW[idx] = wv;
    }

    // Stage 64 input rows x 192 features (x | t1 | t2raw), float4 loads.
    for (int idx = tid; idx < 64 * 48; idx += 256) {
        int row = idx / 48, q = idx % 48;  // k = q*4
        int node = node0 + row;
        float4 v = make_float4(0.f, 0.f, 0.f, 0.f);
        if (node < NN) {
            if (q < 16)       v = ((const float4*)x)[node * 16 + q];
            else if (q < 32)  v = ((const float4*)g_t1)[node * 16 + (q - 16)];
            else              v = ((const float4*)g_t2)[node * 16 + (q - 32)];
        }
        *(float4*)&sA[row * 196 + q * 4] = v;
    }
    __syncthreads();

    const int c4 = tid & 15;   // col group: cols [4*c4, 4*c4+3]
    const int r4 = tid >> 4;   // row group: rows [4*r4, 4*r4+3]
    const int rbase = r4 * 4 * 196;

    float acc[4][4];
#pragma unroll
    for (int i = 0; i < 4; ++i)
#pragma unroll
        for (int j = 0; j < 4; ++j) acc[i][j] = 0.f;

#pragma unroll 4
    for (int k = 0; k < 192; ++k) {
        float4 w = *(const float4*)&sW[k * 64 + c4 * 4];
        float a0 = sA[rbase + k];
        float a1 = sA[rbase + 196 + k];
        float a2 = sA[rbase + 392 + k];
        float a3 = sA[rbase + 588 + k];
        acc[0][0] += a0 * w.x; acc[0][1] += a0 * w.y; acc[0][2] += a0 * w.z; acc[0][3] += a0 * w.w;
        acc[1][0] += a1 * w.x; acc[1][1] += a1 * w.y; acc[1][2] += a1 * w.z; acc[1][3] += a1 * w.w;
        acc[2][0] += a2 * w.x; acc[2][1] += a2 * w.y; acc[2][2] += a2 * w.z; acc[2][3] += a2 * w.w;
        acc[3][0] += a3 * w.x; acc[3][1] += a3 * w.y; acc[3][2] += a3 * w.z; acc[3][3] += a3 * w.w;
    }

    float4 b = ((const float4*)bias)[c4];
#pragma unroll
    for (int i = 0; i < 4; ++i) {
        int node = node0 + r4 * 4 + i;
        if (node < NN) {
            float4 o = make_float4(acc[i][0] + b.x, acc[i][1] + b.y,
                                   acc[i][2] + b.z, acc[i][3] + b.w);
            ((float4*)out)[node * 16 + c4] = o;
        }
    }
}

// ---------------------------------------------------------------------------
extern "C" void kernel_launch(void* const* d_in, const int* in_sizes, int n_in,
                              void* d_out, int out_size) {
    const float* x      = (const float*)d_in[0];
    const int*   rows   = (const int*)d_in[1];
    const int*   cols   = (const int*)d_in[2];
    const float* vals   = (const float*)d_in[3];
    const float* weight = (const float*)d_in[4];
    const float* bias   = (const float*)d_in[5];
    float*       out    = (float*)d_out;

    cudaFuncSetAttribute(gemm_out_kernel,
                         cudaFuncAttributeMaxDynamicSharedMemorySize, GEMM_SMEM);

    build_rowptr<<<(NN + 1 + 255) / 256, 256>>>(rows);
    spmm_kernel<0><<<(NN + 7) / 8, 256>>>(x, cols, vals);
    spmm_kernel<1><<<(NN + 7) / 8, 256>>>(x, cols, vals);
    gemm_out_kernel<<<(NN + 63) / 64, 256, GEMM_SMEM>>>(x, weight, bias, out);
}

// round 2
// speedup vs baseline: 1.0022x; 1.0022x over previous
#include <cuda_runtime.h>
#include <cuda_bf16.h>

#define NN 100000
#define EE 1600000
#define FF 64

// Scratch: Tx1 and raw A@Tx1 (Chebyshev recurrence folded into GEMM weights).
__device__ __align__(16) float g_t1[NN * FF];
__device__ __align__(16) float g_t2[NN * FF];
__device__ int g_rowptr[NN + 1];

// ---------------------------------------------------------------------------
// Kernel 1: CSR row pointers via binary search (rows is sorted).
// ---------------------------------------------------------------------------
__global__ void build_rowptr(const int* __restrict__ rows) {
    int i = blockIdx.x * blockDim.x + threadIdx.x;
    if (i > NN) return;
    int lo = 0, hi = EE;
    while (lo < hi) {
        int mid = (lo + hi) >> 1;
        if (rows[mid] < i) lo = mid + 1; else hi = mid;
    }
    g_rowptr[i] = lo;
}

// ---------------------------------------------------------------------------
// Kernel 2/3: SPMM, warp per row, float2 per lane, 4-edge unroll (MLP=4).
// PASS 0: src = x (param), dst = g_t1.  PASS 1: src = g_t1, dst = g_t2.
// ---------------------------------------------------------------------------
template <int PASS>
__global__ void spmm_kernel(const float* __restrict__ x,
                            const int* __restrict__ cols,
                            const float* __restrict__ vals) {
    int row = blockIdx.x * 8 + (threadIdx.x >> 5);
    if (row >= NN) return;
    int lane = threadIdx.x & 31;

    const float2* __restrict__ h2 =
        (PASS == 0) ? (const float2*)x : (const float2*)g_t1;
    float2* __restrict__ dst =
        (PASS == 0) ? (float2*)g_t1 : (float2*)g_t2;

    int s = g_rowptr[row];
    int e = g_rowptr[row + 1];

    float accx = 0.f, accy = 0.f;
    int i = s;
    for (; i + 4 <= e; i += 4) {
        int   c0 = cols[i],  c1 = cols[i + 1], c2 = cols[i + 2], c3 = cols[i + 3];
        float v0 = vals[i],  v1 = vals[i + 1], v2 = vals[i + 2], v3 = vals[i + 3];
        float2 a = h2[c0 * 32 + lane];
        float2 b = h2[c1 * 32 + lane];
        float2 c = h2[c2 * 32 + lane];
        float2 d = h2[c3 * 32 + lane];
        accx += v0 * a.x; accy += v0 * a.y;
        accx += v1 * b.x; accy += v1 * b.y;
        accx += v2 * c.x; accy += v2 * c.y;
        accx += v3 * d.x; accy += v3 * d.y;
    }
    for (; i < e; ++i) {
        int   c = cols[i];
        float v = vals[i];
        float2 a = h2[c * 32 + lane];
        accx += v * a.x; accy += v * a.y;
    }
    dst[row * 32 + lane] = make_float2(accx, accy);
}

// ---------------------------------------------------------------------------
// Kernel 4: out = [x | t1 | t2raw] @ [W0-W2 ; W1 ; 2*W2] + bias
// Tile: 64 nodes x 64 cols per block, 256 threads, 4x4 register tile each.
// ---------------------------------------------------------------------------
#define GEMM_SMEM (192 * 64 * 4 + 64 * 196 * 4)

__global__ void __launch_bounds__(256, 2)
gemm_out_kernel(const float* __restrict__ x,
                const float* __restrict__ weight,
                const float* __restrict__ bias,
                float* __restrict__ out) {
    extern __shared__ float smem[];
    float* sW = smem;            // [192][64]
    float* sA = smem + 192 * 64; // [64][196] padded

    const int tid = threadIdx.x;
    const int node0 = blockIdx.x * 64;

    // Stage folded weights: k<64 -> W0-W2 ; k<128 -> W1 ; else -> 2*W2
    for (int idx = tid; idx < 192 * 64; idx += 256) {
        int k = idx >> 6, j = idx & 63;
        float wv;
        if (k < 64)        wv = weight[k * 64 + j] - weight[2 * 4096 + k * 64 + j];
        else if (k < 128)  wv = weight[4096 + (k - 64) * 64 + j];
        else               wv = 2.0f * weight[8192 + (k - 128) * 64 + j];
        sW[idx] = wv;
    }

    // Stage 64 input rows x 192 features (x | t1 | t2raw), float4 loads.
    for (int idx = tid; idx < 64 * 48; idx += 256) {
        int row = idx / 48, q = idx % 48;  // k = q*4
        int node = node0 + row;
        float4 v = make_float4(0.f, 0.f, 0.f, 0.f);
        if (node < NN) {
            if (q < 16)       v = ((const float4*)x)[node * 16 + q];
            else if (q < 32)  v = ((const float4*)g_t1)[node * 16 + (q - 16)];
            else              v = ((const float4*)g_t2)[node * 16 + (q - 32)];
        }
        *(float4*)&sA[row * 196 + q * 4] = v;
    }
    __syncthreads();

    const int c4 = tid & 15;   // col group: cols [4*c4, 4*c4+3]
    const int r4 = tid >> 4;   // row group: rows [4*r4, 4*r4+3]
    const int rbase = r4 * 4 * 196;

    float acc[4][4];
#pragma unroll
    for (int i = 0; i < 4; ++i)
#pragma unroll
        for (int j = 0; j < 4; ++j) acc[i][j] = 0.f;

#pragma unroll 4
    for (int k = 0; k < 192; ++k) {
        float4 w = *(const float4*)&sW[k * 64 + c4 * 4];
        float a0 = sA[rbase + k];
        float a1 = sA[rbase + 196 + k];
        float a2 = sA[rbase + 392 + k];
        float a3 = sA[rbase + 588 + k];
        acc[0][0] += a0 * w.x; acc[0][1] += a0 * w.y; acc[0][2] += a0 * w.z; acc[0][3] += a0 * w.w;
        acc[1][0] += a1 * w.x; acc[1][1] += a1 * w.y; acc[1][2] += a1 * w.z; acc[1][3] += a1 * w.w;
        acc[2][0] += a2 * w.x; acc[2][1] += a2 * w.y; acc[2][2] += a2 * w.z; acc[2][3] += a2 * w.w;
        acc[3][0] += a3 * w.x; acc[3][1] += a3 * w.y; acc[3][2] += a3 * w.z; acc[3][3] += a3 * w.w;
    }

    float4 b = ((const float4*)bias)[c4];
#pragma unroll
    for (int i = 0; i < 4; ++i) {
        int node = node0 + r4 * 4 + i;
        if (node < NN) {
            float4 o = make_float4(acc[i][0] + b.x, acc[i][1] + b.y,
                                   acc[i][2] + b.z, acc[i][3] + b.w);
            ((float4*)out)[node * 16 + c4] = o;
        }
    }
}

// ---------------------------------------------------------------------------
extern "C" void kernel_launch(void* const* d_in, const int* in_sizes, int n_in,
                              void* d_out, int out_size) {
    const float* x      = (const float*)d_in[0];
    const int*   rows   = (const int*)d_in[1];
    const int*   cols   = (const int*)d_in[2];
    const float* vals   = (const float*)d_in[3];
    const float* weight = (const float*)d_in[4];
    const float* bias   = (const float*)d_in[5];
    float*       out    = (float*)d_out;

    cudaFuncSetAttribute(gemm_out_kernel,
                         cudaFuncAttributeMaxDynamicSharedMemorySize, GEMM_SMEM);

    build_rowptr<<<(NN + 1 + 255) / 256, 256>>>(rows);
    spmm_kernel<0><<<(NN + 7) / 8, 256>>>(x, cols, vals);
    spmm_kernel<1><<<(NN + 7) / 8, 256>>>(x, cols, vals);
    gemm_out_kernel<<<(NN + 63) / 64, 256, GEMM_SMEM>>>(x, weight, bias, out);
}